// round 1
// baseline (speedup 1.0000x reference)
#include <cuda_runtime.h>
#include <math.h>

#define Bx   128
#define Nx   197
#define Cx   768
#define Hx   12
#define Dx   64
#define NROWS 25216      /* Bx*Nx */
#define LEFT 138
#define CMPL 58
#define NM   139
#define M2   17792       /* Bx*NM */
#define FF   3072

/* ---------------- device scratch (no allocations allowed) ---------------- */
__device__ float g_xn [NROWS*Cx];
__device__ float g_qkv[NROWS*3*Cx];
__device__ float g_ao [NROWS*Cx];
__device__ float g_x1 [NROWS*Cx];
__device__ float g_clsh[Bx*Hx*196];
__device__ float g_cls[Bx*196];
__device__ int   g_idx[Bx*LEFT];
__device__ int   g_cmp[Bx*CMPL];
__device__ float g_NT[Bx*64*Cx];
__device__ float g_XO[Bx*144*Cx];
__device__ float g_nrm[Bx*LEFT];
__device__ float g_D[Bx*64*144];
__device__ int   g_node[Bx*CMPL];
__device__ float g_xm [M2*Cx];
__device__ float g_xn2[M2*Cx];
__device__ float g_h1 [M2*FF];

/* ---------------- LayerNorm: one block per row, 256 thr, C=768 ---------------- */
__global__ __launch_bounds__(256) void ln_kernel(const float* __restrict__ x,
                                                 const float* __restrict__ w,
                                                 const float* __restrict__ bb,
                                                 float* __restrict__ y)
{
    int row = blockIdx.x;
    const float* xr = x + (size_t)row * Cx;
    float* yr = y + (size_t)row * Cx;
    int t = threadIdx.x;
    float v0 = xr[t], v1 = xr[t+256], v2 = xr[t+512];
    float s = v0+v1+v2;
    float q = v0*v0 + v1*v1 + v2*v2;
    __shared__ float sred[16];
    #pragma unroll
    for (int o=16;o;o>>=1){ s += __shfl_xor_sync(0xffffffffu,s,o); q += __shfl_xor_sync(0xffffffffu,q,o); }
    if ((t&31)==0){ sred[t>>5] = s; sred[8+(t>>5)] = q; }
    __syncthreads();
    s = 0.f; q = 0.f;
    #pragma unroll
    for (int i=0;i<8;i++){ s += sred[i]; q += sred[8+i]; }
    float mean = s * (1.0f/768.0f);
    float var  = q * (1.0f/768.0f) - mean*mean;
    float rstd = rsqrtf(var + 1e-5f);
    yr[t]     = (v0-mean)*rstd*w[t]     + bb[t];
    yr[t+256] = (v1-mean)*rstd*w[t+256] + bb[t+256];
    yr[t+512] = (v2-mean)*rstd*w[t+512] + bb[t+512];
}

/* ---------------- SGEMM 128x128x8, 256 thr, 8x8/thread, fp32 ----------------
   EPI: 0 = none, 1 = +bias, 2 = +bias+residual, 3 = +bias+exact GELU        */
template<int EPI>
__global__ __launch_bounds__(256) void sgemm(const float* __restrict__ A,
                                             const float* __restrict__ B,
                                             const float* __restrict__ bias,
                                             const float* __restrict__ res,
                                             float* __restrict__ C,
                                             int M, int N, int K)
{
    __shared__ float As[8][128];
    __shared__ float Bs[8][128];
    int tid = threadIdx.x;
    int bm = blockIdx.y << 7, bn = blockIdx.x << 7;
    const float* Ap = A + (size_t)(bm + (tid>>1))*K + ((tid&1)<<2);
    const float* Bp = B + (size_t)(tid>>5)*N + bn + ((tid&31)<<2);
    int tx = tid & 15, ty = tid >> 4;
    int arow = tid>>1, ac = (tid&1)<<2;
    int brow = tid>>5, bc = (tid&31)<<2;
    float acc[8][8];
    #pragma unroll
    for (int i=0;i<8;i++)
        #pragma unroll
        for (int j=0;j<8;j++) acc[i][j] = 0.f;

    for (int k0=0;k0<K;k0+=8){
        float4 av = *(const float4*)Ap; Ap += 8;
        float4 bv = *(const float4*)Bp; Bp += (size_t)8*N;
        As[ac+0][arow]=av.x; As[ac+1][arow]=av.y; As[ac+2][arow]=av.z; As[ac+3][arow]=av.w;
        *(float4*)&Bs[brow][bc] = bv;
        __syncthreads();
        #pragma unroll
        for (int kk=0;kk<8;kk++){
            float a[8], b[8];
            *(float4*)(a)   = *(const float4*)&As[kk][ty<<3];
            *(float4*)(a+4) = *(const float4*)&As[kk][(ty<<3)+4];
            *(float4*)(b)   = *(const float4*)&Bs[kk][tx<<3];
            *(float4*)(b+4) = *(const float4*)&Bs[kk][(tx<<3)+4];
            #pragma unroll
            for (int i=0;i<8;i++)
                #pragma unroll
                for (int j=0;j<8;j++)
                    acc[i][j] = fmaf(a[i], b[j], acc[i][j]);
        }
        __syncthreads();
    }
    #pragma unroll
    for (int i=0;i<8;i++){
        size_t off = (size_t)(bm + (ty<<3) + i)*N + bn + (tx<<3);
        #pragma unroll
        for (int j=0;j<8;j++){
            float v = acc[i][j];
            if (EPI >= 1) v += bias[bn + (tx<<3) + j];
            if (EPI == 2) v += res[off + j];
            if (EPI == 3) v = 0.5f*v*(1.0f + erff(v*0.70710678118654752f));
            C[off + j] = v;
        }
    }
}

/* ---------------- Attention: one block per (head, batch) ----------------
   Q,K,V (197x64 fp32 each, padded to 65 cols) + per-warp prob rows in smem */
#define QKV_PAD 65
#define QKV_SZ  (Nx*QKV_PAD)            /* 12805 */
#define SMEM_ATTN_FLOATS (3*QKV_SZ + 8*200)
__global__ __launch_bounds__(256) void attn_kernel(const float* __restrict__ qkv,
                                                   float* __restrict__ out,
                                                   float* __restrict__ clsh)
{
    extern __shared__ float sm[];
    float* Qs = sm;
    float* Ks = sm + QKV_SZ;
    float* Vs = sm + 2*QKV_SZ;
    float* Pb = sm + 3*QKV_SZ;
    int h = blockIdx.x, b = blockIdx.y;
    int tid = threadIdx.x, warp = tid>>5, lane = tid&31;

    const float* base = qkv + (size_t)b*Nx*2304 + h*64;
    for (int i = tid; i < Nx*64; i += 256){
        int n = i>>6, c = i&63;
        size_t s = (size_t)n*2304 + c;
        Qs[n*QKV_PAD+c] = base[s];
        Ks[n*QKV_PAD+c] = base[s+768];
        Vs[n*QKV_PAD+c] = base[s+1536];
    }
    __syncthreads();

    float* pb = Pb + warp*200;
    for (int i = warp; i < Nx; i += 8){
        const float* qr = Qs + i*QKV_PAD;
        float sc[7];
        int joff[7];
        #pragma unroll
        for (int t=0;t<7;t++){ sc[t]=0.f; int j=lane+32*t; joff[t] = (j<Nx ? j : 0)*QKV_PAD; }
        #pragma unroll 4
        for (int c=0;c<64;c++){
            float qc = qr[c];
            #pragma unroll
            for (int t=0;t<7;t++) sc[t] = fmaf(qc, Ks[joff[t]+c], sc[t]);
        }
        float mx = -3.0e38f;
        #pragma unroll
        for (int t=0;t<7;t++){
            int j=lane+32*t;
            sc[t] = (j<Nx) ? sc[t]*0.125f : -3.0e38f;
            mx = fmaxf(mx, sc[t]);
        }
        #pragma unroll
        for (int o=16;o;o>>=1) mx = fmaxf(mx, __shfl_xor_sync(0xffffffffu, mx, o));
        float sum = 0.f;
        #pragma unroll
        for (int t=0;t<7;t++){
            int j=lane+32*t;
            float e = (j<Nx) ? expf(sc[t]-mx) : 0.f;
            sc[t]=e; sum+=e;
        }
        #pragma unroll
        for (int o=16;o;o>>=1) sum += __shfl_xor_sync(0xffffffffu, sum, o);
        float inv = 1.0f/sum;
        #pragma unroll
        for (int t=0;t<7;t++){
            int j=lane+32*t;
            if (j<Nx) pb[j] = sc[t]*inv;
        }
        __syncwarp();
        if (i == 0){
            #pragma unroll
            for (int t=0;t<7;t++){
                int j=lane+32*t;
                if (j>=1 && j<Nx) clsh[((size_t)b*Hx + h)*196 + (j-1)] = sc[t]*inv;
            }
        }
        float o0=0.f, o1=0.f;
        for (int j=0;j<Nx;j++){
            float p = pb[j];
            o0 = fmaf(p, Vs[j*QKV_PAD+lane], o0);
            o1 = fmaf(p, Vs[j*QKV_PAD+lane+32], o1);
        }
        size_t oo = (size_t)(b*Nx + i)*Cx + h*64;
        out[oo + lane]      = o0;
        out[oo + lane + 32] = o1;
        __syncwarp();
    }
}

/* ---------------- cls_attn = mean over heads (deterministic) ---------------- */
__global__ void cls_mean_kernel()
{
    int b = blockIdx.x, j = threadIdx.x;
    if (j < 196){
        float s = 0.f;
        #pragma unroll
        for (int h=0; h<Hx; h++) s += g_clsh[((size_t)b*Hx + h)*196 + j];
        g_cls[b*196 + j] = s * (1.0f/12.0f);
    }
}

/* ---------------- top-k (138 of 196) via bitonic sort + complement --------- */
__global__ __launch_bounds__(256) void topk_kernel()
{
    __shared__ float v[256];
    __shared__ int   id[256];
    __shared__ unsigned char sel[196];
    int b = blockIdx.x, t = threadIdx.x;
    v[t]  = (t < 196) ? g_cls[b*196 + t] : -3.0e38f;
    id[t] = t;
    __syncthreads();
    for (int k=2;k<=256;k<<=1){
        for (int j=k>>1;j>0;j>>=1){
            int ixj = t ^ j;
            if (ixj > t){
                float va=v[t], vb=v[ixj];
                int   ia=id[t], ib=id[ixj];
                bool aWorse = (va < vb) || (va == vb && ia > ib);   /* desc, tie->lower idx first */
                bool dirDesc = ((t & k) == 0);
                bool doswap = dirDesc ? aWorse : !aWorse;
                if (doswap){ v[t]=vb; v[ixj]=va; id[t]=ib; id[ixj]=ia; }
            }
            __syncthreads();
        }
    }
    if (t < LEFT) g_idx[b*LEFT + t] = id[t];
    if (t < 196) sel[t] = 0;
    __syncthreads();
    if (t < LEFT) sel[id[t]] = 1;
    __syncthreads();
    if (t == 0){
        int c = 0;
        for (int j=0;j<196;j++) if (!sel[j]) g_cmp[b*CMPL + (c++)] = j;
    }
}

/* ---------------- gathers (padded for the distance GEMM) ---------------- */
__global__ __launch_bounds__(256) void gather_xo_kernel()
{
    int l = blockIdx.x, b = blockIdx.y, t = threadIdx.x;
    float* dst = g_XO + ((size_t)b*144 + l)*Cx;
    float ss = 0.f;
    if (l < LEFT){
        int j = g_idx[b*LEFT + l];
        const float* src = g_x1 + ((size_t)(b*Nx) + 1 + j)*Cx;
        #pragma unroll
        for (int r=0;r<3;r++){
            float vv = src[t + r*256];
            dst[t + r*256] = vv;
            ss += vv*vv;
        }
    } else {
        #pragma unroll
        for (int r=0;r<3;r++) dst[t + r*256] = 0.f;
    }
    __shared__ float sr[8];
    #pragma unroll
    for (int o=16;o;o>>=1) ss += __shfl_xor_sync(0xffffffffu, ss, o);
    if ((t&31)==0) sr[t>>5] = ss;
    __syncthreads();
    if (t == 0 && l < LEFT){
        float tot = 0.f;
        #pragma unroll
        for (int i=0;i<8;i++) tot += sr[i];
        g_nrm[b*LEFT + l] = sqrtf(tot);
    }
}

__global__ __launch_bounds__(256) void gather_nt_kernel()
{
    int m = blockIdx.x, b = blockIdx.y, t = threadIdx.x;
    float* dst = g_NT + ((size_t)b*64 + m)*Cx;
    if (m < CMPL){
        int j = g_cmp[b*CMPL + m];
        const float* src = g_x1 + ((size_t)(b*Nx) + 1 + j)*Cx;
        #pragma unroll
        for (int r=0;r<3;r++) dst[t + r*256] = src[t + r*256];
    } else {
        #pragma unroll
        for (int r=0;r<3;r++) dst[t + r*256] = 0.f;
    }
}

/* ---------------- distance GEMM: per batch, D[64pad,144pad] = NT @ XO^T ---- */
__global__ __launch_bounds__(256) void dist_kernel()
{
    __shared__ float NTs[64*33];
    __shared__ float XOs[144*33];
    int b = blockIdx.x, tid = threadIdx.x;
    int tx = tid & 15, ty = tid >> 4;
    const float* NTb = g_NT + (size_t)b*64*Cx;
    const float* XOb = g_XO + (size_t)b*144*Cx;
    float acc[4][9];
    #pragma unroll
    for (int i=0;i<4;i++)
        #pragma unroll
        for (int j=0;j<9;j++) acc[i][j]=0.f;

    for (int k0=0;k0<Cx;k0+=32){
        for (int i=tid;i<64*32;i+=256){ int m=i>>5, kk=i&31; NTs[m*33+kk]=NTb[(size_t)m*Cx+k0+kk]; }
        for (int i=tid;i<144*32;i+=256){ int l=i>>5, kk=i&31; XOs[l*33+kk]=XOb[(size_t)l*Cx+k0+kk]; }
        __syncthreads();
        #pragma unroll 8
        for (int kk=0;kk<32;kk++){
            float a[4], bb2[9];
            #pragma unroll
            for (int ii=0;ii<4;ii++) a[ii]  = NTs[(ty*4+ii)*33 + kk];
            #pragma unroll
            for (int jj=0;jj<9;jj++) bb2[jj]= XOs[(tx*9+jj)*33 + kk];
            #pragma unroll
            for (int ii=0;ii<4;ii++)
                #pragma unroll
                for (int jj=0;jj<9;jj++)
                    acc[ii][jj] = fmaf(a[ii], bb2[jj], acc[ii][jj]);
        }
        __syncthreads();
    }
    #pragma unroll
    for (int ii=0;ii<4;ii++)
        #pragma unroll
        for (int jj=0;jj<9;jj++)
            g_D[(size_t)b*9216 + (ty*4+ii)*144 + (tx*9+jj)] = acc[ii][jj];
}

/* ---------------- argmax over topk (first-max tie rule, matches jnp) ------- */
__global__ void argmax_kernel()
{
    int m = blockIdx.x, b = blockIdx.y, lane = threadIdx.x;
    const float* Dr = g_D + (size_t)b*9216 + m*144;
    float best = -3.0e38f; int bi = 1<<30;
    for (int l=lane; l<LEFT; l+=32){
        float v = Dr[l] / g_nrm[b*LEFT + l];
        if (v > best || (v == best && l < bi)){ best = v; bi = l; }
    }
    #pragma unroll
    for (int o=16;o;o>>=1){
        float v2 = __shfl_xor_sync(0xffffffffu, best, o);
        int   i2 = __shfl_xor_sync(0xffffffffu, bi,   o);
        if (v2 > best || (v2 == best && i2 < bi)){ best = v2; bi = i2; }
    }
    if (lane == 0) g_node[b*CMPL + m] = bi;
}

/* ---------------- deterministic merge (no atomics): one block per (l,b) ---- */
__global__ __launch_bounds__(256) void merge_kernel()
{
    int l = blockIdx.x, b = blockIdx.y, t = threadIdx.x;
    int jt = g_idx[b*LEFT + l];
    float w = g_cls[b*196 + jt];
    const float* src = g_x1 + ((size_t)(b*Nx) + 1 + jt)*Cx;
    float a0 = src[t]*w, a1 = src[t+256]*w, a2 = src[t+512]*w;
    float tka = w;
    for (int m=0;m<CMPL;m++){
        if (g_node[b*CMPL + m] == l){
            int jm = g_cmp[b*CMPL + m];
            float wm = g_cls[b*196 + jm];
            const float* s2 = g_x1 + ((size_t)(b*Nx) + 1 + jm)*Cx;
            a0 += s2[t]*wm; a1 += s2[t+256]*wm; a2 += s2[t+512]*wm;
            tka += wm;
        }
    }
    float* dst = g_xm + ((size_t)(b*NM) + 1 + l)*Cx;
    dst[t]     = a0 / tka;
    dst[t+256] = a1 / tka;
    dst[t+512] = a2 / tka;
}

__global__ void copy_cls_kernel()
{
    int b = blockIdx.x, t = threadIdx.x;
    const float* s = g_x1 + (size_t)b*Nx*Cx;
    float* d = g_xm + (size_t)b*NM*Cx;
    #pragma unroll
    for (int r=0;r<3;r++) d[t + r*256] = s[t + r*256];
}

/* ---------------- host launcher ---------------- */
extern "C" void kernel_launch(void* const* d_in, const int* in_sizes, int n_in,
                              void* d_out, int out_size)
{
    const float* x     = (const float*)d_in[0];
    const float* n1w   = (const float*)d_in[1];
    const float* n1b   = (const float*)d_in[2];
    const float* qkvw  = (const float*)d_in[3];
    const float* projw = (const float*)d_in[4];
    const float* projb = (const float*)d_in[5];
    const float* n2w   = (const float*)d_in[6];
    const float* n2b   = (const float*)d_in[7];
    const float* fc1w  = (const float*)d_in[8];
    const float* fc1b  = (const float*)d_in[9];
    const float* fc2w  = (const float*)d_in[10];
    const float* fc2b  = (const float*)d_in[11];
    float* out = (float*)d_out;

    void *p;
    cudaGetSymbolAddress(&p, g_xn);   float* pxn  = (float*)p;
    cudaGetSymbolAddress(&p, g_qkv);  float* pqkv = (float*)p;
    cudaGetSymbolAddress(&p, g_ao);   float* pao  = (float*)p;
    cudaGetSymbolAddress(&p, g_x1);   float* px1  = (float*)p;
    cudaGetSymbolAddress(&p, g_clsh); float* pclsh= (float*)p;
    cudaGetSymbolAddress(&p, g_xm);   float* pxm  = (float*)p;
    cudaGetSymbolAddress(&p, g_xn2);  float* pxn2 = (float*)p;
    cudaGetSymbolAddress(&p, g_h1);   float* ph1  = (float*)p;

    /* 1) LN1 */
    ln_kernel<<<NROWS, 256>>>(x, n1w, n1b, pxn);

    /* 2) QKV GEMM: [25216,768] x [768,2304] */
    sgemm<0><<<dim3(2304/128, NROWS/128), 256>>>(pxn, qkvw, nullptr, nullptr, pqkv,
                                                 NROWS, 2304, Cx);

    /* 3) attention per (head, batch) */
    cudaFuncSetAttribute(attn_kernel, cudaFuncAttributeMaxDynamicSharedMemorySize,
                         SMEM_ATTN_FLOATS*4);
    attn_kernel<<<dim3(Hx, Bx), 256, SMEM_ATTN_FLOATS*4>>>(pqkv, pao, pclsh);

    /* 4) proj GEMM + bias + residual(x) -> x1 */
    sgemm<2><<<dim3(Cx/128, NROWS/128), 256>>>(pao, projw, projb, x, px1,
                                               NROWS, Cx, Cx);

    /* 5) cls attention mean over heads, 6) top-k + complement */
    cls_mean_kernel<<<Bx, 256>>>();
    topk_kernel<<<Bx, 256>>>();

    /* 7) gathers + norms, 8) cosine distance GEMM, 9) argmax */
    gather_xo_kernel<<<dim3(144, Bx), 256>>>();
    gather_nt_kernel<<<dim3(64, Bx), 256>>>();
    dist_kernel<<<Bx, 256>>>();
    argmax_kernel<<<dim3(CMPL, Bx), 32>>>();

    /* 10) deterministic merge + cls copy -> xm */
    merge_kernel<<<dim3(LEFT, Bx), 256>>>();
    copy_cls_kernel<<<Bx, 256>>>();

    /* 11) LN2, 12) fc1+GELU, 13) fc2+bias+residual -> out */
    ln_kernel<<<M2, 256>>>(pxm, n2w, n2b, pxn2);
    sgemm<3><<<dim3(FF/128, M2/128), 256>>>(pxn2, fc1w, fc1b, nullptr, ph1,
                                            M2, FF, Cx);
    sgemm<2><<<dim3(Cx/128, M2/128), 256>>>(ph1, fc2w, fc2b, pxm, out,
                                            M2, Cx, FF);
    (void)in_sizes; (void)n_in; (void)out_size;
}